// round 13
// baseline (speedup 1.0000x reference)
#include <cuda_runtime.h>
#include <cstdint>

#define PP 32
#define BB 512
#define II 1024
#define OO 1024

#define BM 128
#define BN 128
#define BK 128          // int8 k-bytes per stage
#define STAGES 3
#define KITERS (II / BK)   // 8

#define PREP_CTAS 128
#define GEMM_CTAS (PP * (BB / BM) * (OO / BN))   // 1024
#define TOTAL_CTAS (PREP_CTAS + GEMM_CTAS)       // 1152

// ---------------- scratch (static device globals; no runtime allocation) ----------------
__device__ __align__(16) int8_t g_x8[(size_t)PP * BB * II];   // 16 MB  [p][b][i]
__device__ __align__(16) int8_t g_w8[(size_t)PP * OO * II];   // 32 MB  [p][o][i] (K-major)
__device__ int g_bias[PP * OO];                               // colsum_i(w1)
__device__ int g_flag[PP];                                    // prep completion per p
__device__ unsigned g_ticket;                                 // work dispatcher

#define SW128(x) ((x) ^ (((x) >> 3) & 0x70))

__device__ __forceinline__ uint32_t smem_u32(const void* p) {
    uint32_t a;
    asm("{ .reg .u64 t; cvta.to.shared.u64 t, %1; cvt.u32.u64 %0, t; }" : "=r"(a) : "l"(p));
    return a;
}

__device__ __forceinline__ void cp_async16(uint32_t dst, const void* src) {
    asm volatile("cp.async.cg.shared.global [%0], [%1], 16;" :: "r"(dst), "l"(src) : "memory");
}
__device__ __forceinline__ void cp_commit() {
    asm volatile("cp.async.commit_group;" ::: "memory");
}
__device__ __forceinline__ void cp_wait2() {
    asm volatile("cp.async.wait_group 2;" ::: "memory");
}

__device__ __forceinline__ void ldsm4(uint32_t* r, uint32_t addr) {
    asm volatile("ldmatrix.sync.aligned.m8n8.x4.shared.b16 {%0,%1,%2,%3}, [%4];"
                 : "=r"(r[0]), "=r"(r[1]), "=r"(r[2]), "=r"(r[3]) : "r"(addr));
}

__device__ __forceinline__ void mma_s8(int* c, const uint32_t* a, uint32_t b0, uint32_t b1) {
    asm volatile(
        "mma.sync.aligned.m16n8k32.row.col.s32.s8.s8.s32 "
        "{%0,%1,%2,%3}, {%4,%5,%6,%7}, {%8,%9}, {%0,%1,%2,%3};"
        : "+r"(c[0]), "+r"(c[1]), "+r"(c[2]), "+r"(c[3])
        : "r"(a[0]), "r"(a[1]), "r"(a[2]), "r"(a[3]), "r"(b0), "r"(b1));
}

// bit of a {0.0f,1.0f} float: exponent LSB
__device__ __forceinline__ uint32_t fbit(float f) {
    return (__float_as_uint(f) >> 23) & 1u;
}

// ---------------- Pass 1: x fp32 -> s8; zero bias/flags/ticket ----------------
__global__ void __launch_bounds__(256) k_convert_x(const float* __restrict__ x) {
    size_t t = (size_t)blockIdx.x * 256 + threadIdx.x;
    const float4* xv = reinterpret_cast<const float4*>(x) + t * 4;
    uint32_t w[4];
    #pragma unroll
    for (int j = 0; j < 4; j++) {
        float4 v = xv[j];
        w[j] = fbit(v.x) | (fbit(v.y) << 8) | (fbit(v.z) << 16) | (fbit(v.w) << 24);
    }
    reinterpret_cast<uint4*>(g_x8)[t] = make_uint4(w[0], w[1], w[2], w[3]);
    if (blockIdx.x < 32) {      // zero bias: 32 blocks x 256 x int4 = 32768 ints
        reinterpret_cast<int4*>(g_bias)[blockIdx.x * 256 + threadIdx.x] = make_int4(0, 0, 0, 0);
    }
    if (blockIdx.x == 32) {     // zero flags + ticket
        if (threadIdx.x < PP) g_flag[threadIdx.x] = 0;
        if (threadIdx.x == PP) g_ticket = 0;
    }
}

// ---------------- Pass 2: fused producer (w prep) + consumer (R4 hybrid GEMM) ----------------
// gemm smem: 3 stages x (A 16KB + B 16KB) = 96 KB dynamic
#define STAGE_BYTES 32768
#define SMEM_TOTAL (STAGES * STAGE_BYTES)

__device__ __forceinline__ void fill_stage(int p, int bm0, int bn0, int k0,
                                           uint32_t sbase, int s, int tid) {
    uint32_t st = sbase + s * STAGE_BYTES;
    const int8_t* xb = g_x8 + ((size_t)p * BB + bm0) * II + k0;
    const int8_t* wb = g_w8 + ((size_t)p * OO + bn0) * II + k0;
    #pragma unroll
    for (int jj = 0; jj < 4; jj++) {            // A: 1024 chunks of 16B
        int idx = jj * 256 + tid;
        int row = idx >> 3, c = idx & 7;
        cp_async16(st + SW128(row * 128 + c * 16), xb + (size_t)row * II + c * 16);
    }
    #pragma unroll
    for (int jj = 0; jj < 4; jj++) {            // B: 1024 chunks of 16B
        int idx = jj * 256 + tid;
        int row = idx >> 3, c = idx & 7;
        cp_async16(st + 16384 + SW128(row * 128 + c * 16), wb + (size_t)row * II + c * 16);
    }
}

__global__ void __launch_bounds__(256, 1) k_fused(const float* __restrict__ w,
                                                  float* __restrict__ out) {
    __shared__ unsigned sticket;
    __shared__ int8_t tile[32][36];
    __shared__ int sbias[32];
    extern __shared__ char smem[];
    uint32_t sbase = smem_u32(smem);
    int tid  = threadIdx.x;

    if (tid == 0) sticket = atomicAdd(&g_ticket, 1u);
    __syncthreads();
    unsigned id = sticket;

    if (id < PREP_CTAS) {
        // ================= producer: 1/128 of each p's w transpose + bias =================
        int c = id;
        for (int p = 0; p < PP; p++) {
            #pragma unroll 1
            for (int j = 0; j < 8; j++) {
                int tileIdx = c * 8 + j;             // 0..1023 over (i_t, o_t)
                int i0 = (tileIdx >> 5) * 32;
                int o0 = (tileIdx & 31) * 32;

                if (tid < 32) sbias[tid] = 0;
                __syncthreads();

                int r = tid >> 3, cc = tid & 7;
                size_t off = ((size_t)p * II + (i0 + r)) * OO + o0 + cc * 4;
                float4 a = *reinterpret_cast<const float4*>(w + off);
                float4 b = *reinterpret_cast<const float4*>(w + off + (size_t)PP * II * OO);
                int a0 = fbit(a.x), a1 = fbit(a.y), a2 = fbit(a.z), a3 = fbit(a.w);
                int b0 = fbit(b.x), b1 = fbit(b.y), b2 = fbit(b.z), b3 = fbit(b.w);
                tile[r][cc * 4 + 0] = (int8_t)(a0 - b0);
                tile[r][cc * 4 + 1] = (int8_t)(a1 - b1);
                tile[r][cc * 4 + 2] = (int8_t)(a2 - b2);
                tile[r][cc * 4 + 3] = (int8_t)(a3 - b3);
                atomicAdd(&sbias[cc * 4 + 0], b0);
                atomicAdd(&sbias[cc * 4 + 1], b1);
                atomicAdd(&sbias[cc * 4 + 2], b2);
                atomicAdd(&sbias[cc * 4 + 3], b3);
                __syncthreads();

                int rr = tid >> 3, c2 = tid & 7;
                uint32_t v = (uint32_t)(uint8_t)tile[c2 * 4 + 0][rr]
                           | ((uint32_t)(uint8_t)tile[c2 * 4 + 1][rr] << 8)
                           | ((uint32_t)(uint8_t)tile[c2 * 4 + 2][rr] << 16)
                           | ((uint32_t)(uint8_t)tile[c2 * 4 + 3][rr] << 24);
                *reinterpret_cast<uint32_t*>(
                    g_w8 + ((size_t)p * OO + (o0 + rr)) * II + i0 + c2 * 4) = v;

                if (tid < 32) atomicAdd(&g_bias[p * OO + o0 + tid], sbias[tid]);
                __syncthreads();
            }
            __threadfence();            // each thread publishes its stores for this p
            __syncthreads();
            if (tid == 0) atomicAdd(&g_flag[p], 1);
        }
        return;
    }

    // ================= consumer: R4 hybrid GEMM tile (ordered by p) =================
    int t0  = id - PREP_CTAS;
    int p   = t0 >> 5;                  // p increases with ticket -> earliest flags first
    int rem = t0 & 31;
    int bn0 = (rem & 7) * BN;
    int bm0 = (rem >> 3) * BM;

    // wait for this p's weights + bias
    if (tid == 0) {
        volatile int* f = &g_flag[p];
        while (*f < PREP_CTAS) __nanosleep(128);
        __threadfence();
    }
    __syncthreads();

    int wid  = tid >> 5;
    int lane = tid & 31;
    bool is_tensor = (wid < 4);
    int wm = is_tensor ? wid : (wid - 4);

    int tacc[2][8][4];
    int dacc[8][8];
    int aoff[8], asw[8], boff[8], bsw;

    if (is_tensor) {
        #pragma unroll
        for (int mt = 0; mt < 2; mt++)
            #pragma unroll
            for (int nt = 0; nt < 8; nt++)
                #pragma unroll
                for (int j = 0; j < 4; j++) tacc[mt][nt][j] = 0;
    } else {
        #pragma unroll
        for (int ii = 0; ii < 8; ii++)
            #pragma unroll
            for (int jj = 0; jj < 8; jj++) dacc[ii][jj] = 0;
        int ty = lane >> 3;
        int tx = lane & 7;
        #pragma unroll
        for (int ii = 0; ii < 8; ii++) {
            int row = wm * 32 + ty + 4 * ii;     // distinct row&7 across ty -> conflict-free
            aoff[ii] = row * 128;
            asw[ii]  = (row & 7) * 16;
        }
        #pragma unroll
        for (int jj = 0; jj < 8; jj++)
            boff[jj] = 16384 + (64 + tx + 8 * jj) * 128;   // col&7 = tx -> conflict-free
        bsw = tx * 16;
    }

    // prologue: stages 0,1
    fill_stage(p, bm0, bn0, 0, sbase, 0, tid); cp_commit();
    fill_stage(p, bm0, bn0, BK, sbase, 1, tid); cp_commit();

    int lr = lane & 7, grp = lane >> 3;

    for (int i = 0; i < KITERS; i++) {
        __syncthreads();                    // prior-iter smem reads complete
        if (i + 2 < KITERS)
            fill_stage(p, bm0, bn0, (i + 2) * BK, sbase, (i + 2) % STAGES, tid);
        cp_commit();
        cp_wait2();                         // stage i complete
        __syncthreads();

        int s = i % STAGES;

        if (is_tensor) {
            uint32_t abase = sbase + s * STAGE_BYTES;
            uint32_t bbase = abase + 16384;
            #pragma unroll
            for (int ks = 0; ks < 4; ks++) {
                uint32_t afr[2][4];
                #pragma unroll
                for (int mt = 0; mt < 2; mt++) {
                    int row = wm * 32 + mt * 16 + ((grp & 1) << 3) + lr;
                    uint32_t off = row * 128 + ((ks << 1) + (grp >> 1)) * 16;
                    ldsm4(afr[mt], abase + SW128(off));
                }
                uint32_t bfr[4][4];
                #pragma unroll
                for (int np = 0; np < 4; np++) {
                    int row = np * 16 + ((grp >> 1) << 3) + lr;   // B rows 0-63 (cols 0-64)
                    uint32_t off = row * 128 + ((ks << 1) + (grp & 1)) * 16;
                    ldsm4(bfr[np], bbase + SW128(off));
                }
                #pragma unroll
                for (int mt = 0; mt < 2; mt++)
                    #pragma unroll
                    for (int np = 0; np < 4; np++) {
                        mma_s8(tacc[mt][np * 2 + 0], afr[mt], bfr[np][0], bfr[np][1]);
                        mma_s8(tacc[mt][np * 2 + 1], afr[mt], bfr[np][2], bfr[np][3]);
                    }
            }
        } else {
            const char* sb = smem + s * STAGE_BYTES;
            #pragma unroll 4
            for (int kq = 0; kq < 32; kq += 2) {
                int k4 = kq * 4;
                int2 av[8], bv[8];
                #pragma unroll
                for (int ii = 0; ii < 8; ii++)
                    av[ii] = *reinterpret_cast<const int2*>(sb + aoff[ii] + (k4 ^ asw[ii]));
                #pragma unroll
                for (int jj = 0; jj < 8; jj++)
                    bv[jj] = *reinterpret_cast<const int2*>(sb + boff[jj] + (k4 ^ bsw));
                #pragma unroll
                for (int ii = 0; ii < 8; ii++)
                    #pragma unroll
                    for (int jj = 0; jj < 8; jj++) {
                        int a0 = dacc[ii][jj];
                        a0 = __dp4a(av[ii].x, bv[jj].x, a0);
                        a0 = __dp4a(av[ii].y, bv[jj].y, a0);
                        dacc[ii][jj] = a0;
                    }
            }
        }
    }

    // epilogue: add integer bias, convert to f32, store
    if (is_tensor) {
        #pragma unroll
        for (int nt = 0; nt < 8; nt++) {
            int col = bn0 + nt * 8 + ((lane & 3) << 1);
            int2 bv = *reinterpret_cast<const int2*>(&g_bias[p * OO + col]);
            #pragma unroll
            for (int mt = 0; mt < 2; mt++) {
                int row0 = bm0 + wm * 32 + mt * 16 + (lane >> 2);
                float2 v0, v1;
                v0.x = (float)(tacc[mt][nt][0] + bv.x);
                v0.y = (float)(tacc[mt][nt][1] + bv.y);
                v1.x = (float)(tacc[mt][nt][2] + bv.x);
                v1.y = (float)(tacc[mt][nt][3] + bv.y);
                *reinterpret_cast<float2*>(out + ((size_t)p * BB + row0) * OO + col) = v0;
                *reinterpret_cast<float2*>(out + ((size_t)p * BB + row0 + 8) * OO + col) = v1;
            }
        }
    } else {
        int ty = lane >> 3;
        int tx = lane & 7;
        int biasr[8];
        #pragma unroll
        for (int jj = 0; jj < 8; jj++)
            biasr[jj] = g_bias[p * OO + bn0 + 64 + tx + 8 * jj];
        #pragma unroll
        for (int ii = 0; ii < 8; ii++) {
            int row = bm0 + wm * 32 + ty + 4 * ii;
            float* orow = out + ((size_t)p * BB + row) * OO + bn0 + 64 + tx;
            #pragma unroll
            for (int jj = 0; jj < 8; jj++)
                orow[8 * jj] = (float)(dacc[ii][jj] + biasr[jj]);
        }
    }
}

// ---------------- launch ----------------
extern "C" void kernel_launch(void* const* d_in, const int* in_sizes, int n_in,
                              void* d_out, int out_size) {
    const float* x = (const float*)d_in[0];
    const float* w = (const float*)d_in[1];
    if (n_in >= 2 && in_sizes[0] > in_sizes[1]) {   // safety: x is the smaller tensor
        const float* t = x; x = w; w = t;
    }
    float* out = (float*)d_out;

    static bool attr_set = false;
    if (!attr_set) {
        cudaFuncSetAttribute(k_fused, cudaFuncAttributeMaxDynamicSharedMemorySize, SMEM_TOTAL);
        attr_set = true;
    }

    k_convert_x<<<(PP * BB * II) / (16 * 256), 256>>>(x);
    k_fused<<<TOTAL_CTAS, 256, SMEM_TOTAL>>>(w, out);
}

// round 14
// speedup vs baseline: 1.7420x; 1.7420x over previous
#include <cuda_runtime.h>
#include <cstdint>

#define PP 32
#define BB 512
#define II 1024
#define OO 1024

#define BM 128
#define BN 128
#define BK 128          // int8 k-bytes per stage
#define STAGES 3
#define KITERS (II / BK)   // 8

#define PGROUP 4            // p's per pipeline chunk
#define NGROUPS (PP / PGROUP)   // 8

// ---------------- scratch (static device globals; no runtime allocation) ----------------
__device__ __align__(16) int8_t g_x8[(size_t)PP * BB * II];   // 16 MB  [p][b][i]
__device__ __align__(16) int8_t g_w8[(size_t)PP * OO * II];   // 32 MB  [p][o][i] (K-major)
__device__ int g_bias[PP * OO];                               // colsum_i(w1)

#define SW128(x) ((x) ^ (((x) >> 3) & 0x70))

__device__ __forceinline__ uint32_t smem_u32(const void* p) {
    uint32_t a;
    asm("{ .reg .u64 t; cvta.to.shared.u64 t, %1; cvt.u32.u64 %0, t; }" : "=r"(a) : "l"(p));
    return a;
}

__device__ __forceinline__ void cp_async16(uint32_t dst, const void* src) {
    asm volatile("cp.async.cg.shared.global [%0], [%1], 16;" :: "r"(dst), "l"(src) : "memory");
}
__device__ __forceinline__ void cp_commit() {
    asm volatile("cp.async.commit_group;" ::: "memory");
}
__device__ __forceinline__ void cp_wait2() {
    asm volatile("cp.async.wait_group 2;" ::: "memory");
}

__device__ __forceinline__ void ldsm4(uint32_t* r, uint32_t addr) {
    asm volatile("ldmatrix.sync.aligned.m8n8.x4.shared.b16 {%0,%1,%2,%3}, [%4];"
                 : "=r"(r[0]), "=r"(r[1]), "=r"(r[2]), "=r"(r[3]) : "r"(addr));
}

__device__ __forceinline__ void mma_s8(int* c, const uint32_t* a, uint32_t b0, uint32_t b1) {
    asm volatile(
        "mma.sync.aligned.m16n8k32.row.col.s32.s8.s8.s32 "
        "{%0,%1,%2,%3}, {%4,%5,%6,%7}, {%8,%9}, {%0,%1,%2,%3};"
        : "+r"(c[0]), "+r"(c[1]), "+r"(c[2]), "+r"(c[3])
        : "r"(a[0]), "r"(a[1]), "r"(a[2]), "r"(a[3]), "r"(b0), "r"(b1));
}

// bit of a {0.0f,1.0f} float: exponent LSB
__device__ __forceinline__ uint32_t fbit(float f) {
    return (__float_as_uint(f) >> 23) & 1u;
}

// ---------------- Pass 1: x fp32 -> s8 (16 floats / thread); also zero g_bias ----------------
__global__ void __launch_bounds__(256) k_convert_x(const float* __restrict__ x) {
    size_t t = (size_t)blockIdx.x * 256 + threadIdx.x;
    const float4* xv = reinterpret_cast<const float4*>(x) + t * 4;
    uint32_t w[4];
    #pragma unroll
    for (int j = 0; j < 4; j++) {
        float4 v = xv[j];
        w[j] = fbit(v.x) | (fbit(v.y) << 8) | (fbit(v.z) << 16) | (fbit(v.w) << 24);
    }
    reinterpret_cast<uint4*>(g_x8)[t] = make_uint4(w[0], w[1], w[2], w[3]);
    if (blockIdx.x < 32) {      // zero bias: 32 blocks x 256 x int4 = 32768 ints
        reinterpret_cast<int4*>(g_bias)[blockIdx.x * 256 + threadIdx.x] = make_int4(0, 0, 0, 0);
    }
}

// ---------------- Pass 2 (chunked by p-group): w' transpose + bias ----------------
__global__ void __launch_bounds__(256) k_prep_w(const float* __restrict__ w, int pbase) {
    __shared__ int8_t tile[32][36];
    __shared__ int sbias[32];
    int t = threadIdx.x;
    int p = pbase + blockIdx.z;
    int i0 = blockIdx.x * 32;
    int o0 = blockIdx.y * 32;

    if (t < 32) sbias[t] = 0;
    __syncthreads();

    int r = t >> 3, c = t & 7;
    size_t off = ((size_t)p * II + (i0 + r)) * OO + o0 + c * 4;
    float4 a = *reinterpret_cast<const float4*>(w + off);
    float4 b = *reinterpret_cast<const float4*>(w + off + (size_t)PP * II * OO);
    int a0 = fbit(a.x), a1 = fbit(a.y), a2 = fbit(a.z), a3 = fbit(a.w);
    int b0 = fbit(b.x), b1 = fbit(b.y), b2 = fbit(b.z), b3 = fbit(b.w);
    tile[r][c * 4 + 0] = (int8_t)(a0 - b0);
    tile[r][c * 4 + 1] = (int8_t)(a1 - b1);
    tile[r][c * 4 + 2] = (int8_t)(a2 - b2);
    tile[r][c * 4 + 3] = (int8_t)(a3 - b3);
    atomicAdd(&sbias[c * 4 + 0], b0);
    atomicAdd(&sbias[c * 4 + 1], b1);
    atomicAdd(&sbias[c * 4 + 2], b2);
    atomicAdd(&sbias[c * 4 + 3], b3);
    __syncthreads();

    int rr = t >> 3, cc = t & 7;
    uint32_t v = (uint32_t)(uint8_t)tile[cc * 4 + 0][rr]
               | ((uint32_t)(uint8_t)tile[cc * 4 + 1][rr] << 8)
               | ((uint32_t)(uint8_t)tile[cc * 4 + 2][rr] << 16)
               | ((uint32_t)(uint8_t)tile[cc * 4 + 3][rr] << 24);
    *reinterpret_cast<uint32_t*>(g_w8 + ((size_t)p * OO + (o0 + rr)) * II + i0 + cc * 4) = v;

    if (t < 32) atomicAdd(&g_bias[p * OO + o0 + t], sbias[t]);
}

// ---------------- Pass 3 (chunked by p-group): R4 hybrid GEMM, reg-capped ----------------
// smem: 3 stages x 32 KB = 96 KB used, padded to 120 KB to pin 1 CTA/SM (leaves RF room
// for co-resident prep CTAs).
#define STAGE_BYTES 32768
#define SMEM_TOTAL (120 * 1024)

__device__ __forceinline__ void fill_stage(int p, int bm0, int bn0, int k0,
                                           uint32_t sbase, int s, int tid) {
    uint32_t st = sbase + s * STAGE_BYTES;
    const int8_t* xb = g_x8 + ((size_t)p * BB + bm0) * II + k0;
    const int8_t* wb = g_w8 + ((size_t)p * OO + bn0) * II + k0;
    #pragma unroll
    for (int jj = 0; jj < 4; jj++) {            // A: 1024 chunks of 16B
        int idx = jj * 256 + tid;
        int row = idx >> 3, c = idx & 7;
        cp_async16(st + SW128(row * 128 + c * 16), xb + (size_t)row * II + c * 16);
    }
    #pragma unroll
    for (int jj = 0; jj < 4; jj++) {            // B: 1024 chunks of 16B
        int idx = jj * 256 + tid;
        int row = idx >> 3, c = idx & 7;
        cp_async16(st + 16384 + SW128(row * 128 + c * 16), wb + (size_t)row * II + c * 16);
    }
}

__global__ void __launch_bounds__(256, 2) k_gemm(float* __restrict__ out, int pbase) {
    extern __shared__ char smem[];
    uint32_t sbase = smem_u32(smem);
    int tid  = threadIdx.x;
    int wid  = tid >> 5;
    int lane = tid & 31;

    int p   = pbase + blockIdx.z;
    int bm0 = blockIdx.y * BM;
    int bn0 = blockIdx.x * BN;

    bool is_tensor = (wid < 4);
    int wm = is_tensor ? wid : (wid - 4);   // row group (32 rows each)

    // single accumulator file shared by both paths (disjoint per-thread use -> low regs)
    int acc[64];
    #pragma unroll
    for (int j = 0; j < 64; j++) acc[j] = 0;

    // prologue: stages 0,1
    fill_stage(p, bm0, bn0, 0, sbase, 0, tid); cp_commit();
    fill_stage(p, bm0, bn0, BK, sbase, 1, tid); cp_commit();

    int lr = lane & 7, grp = lane >> 3;
    int ty = lane >> 3, tx = lane & 7;
    int arow_base = (wm * 32 + ty) * 128;           // dp4a A: + 512*ii
    int asw_base  = ty * 16;                        // ^ ((ii&1)<<6)
    int bcol_base = 16384 + (64 + tx) * 128;        // dp4a B: + 1024*jj
    int bsw = tx * 16;

    for (int i = 0; i < KITERS; i++) {
        __syncthreads();                    // prior-iter smem reads complete
        if (i + 2 < KITERS)
            fill_stage(p, bm0, bn0, (i + 2) * BK, sbase, (i + 2) % STAGES, tid);
        cp_commit();
        cp_wait2();                         // stage i complete
        __syncthreads();

        int s = i % STAGES;

        if (is_tensor) {
            // tensor warps 0-3: cols [0,64), rows wm*32..+32
            uint32_t abase = sbase + s * STAGE_BYTES;
            uint32_t bbase = abase + 16384;
            #pragma unroll
            for (int ks = 0; ks < 4; ks++) {
                uint32_t afr[2][4];
                #pragma unroll
                for (int mt = 0; mt < 2; mt++) {
                    int row = wm * 32 + mt * 16 + ((grp & 1) << 3) + lr;
                    uint32_t off = row * 128 + ((ks << 1) + (grp >> 1)) * 16;
                    ldsm4(afr[mt], abase + SW128(off));
                }
                uint32_t bfr[4][4];
                #pragma unroll
                for (int np = 0; np < 4; np++) {
                    int row = np * 16 + ((grp >> 1) << 3) + lr;   // B rows 0-63
                    uint32_t off = row * 128 + ((ks << 1) + (grp & 1)) * 16;
                    ldsm4(bfr[np], bbase + SW128(off));
                }
                #pragma unroll
                for (int mt = 0; mt < 2; mt++)
                    #pragma unroll
                    for (int np = 0; np < 4; np++) {
                        mma_s8(&acc[mt * 32 + (np * 2 + 0) * 4], afr[mt], bfr[np][0], bfr[np][1]);
                        mma_s8(&acc[mt * 32 + (np * 2 + 1) * 4], afr[mt], bfr[np][2], bfr[np][3]);
                    }
            }
        } else {
            // dp4a warps 4-7: cols [64,128), rows wm*32..+32, 8x8/thread
            const char* sb = smem + s * STAGE_BYTES;
            #pragma unroll 4
            for (int kq = 0; kq < 32; kq += 2) {
                int k4 = kq * 4;
                int2 av[8], bv[8];
                #pragma unroll
                for (int ii = 0; ii < 8; ii++)
                    av[ii] = *reinterpret_cast<const int2*>(
                        sb + arow_base + 512 * ii + (k4 ^ (asw_base ^ ((ii & 1) << 6))));
                #pragma unroll
                for (int jj = 0; jj < 8; jj++)
                    bv[jj] = *reinterpret_cast<const int2*>(
                        sb + bcol_base + 1024 * jj + (k4 ^ bsw));
                #pragma unroll
                for (int ii = 0; ii < 8; ii++)
                    #pragma unroll
                    for (int jj = 0; jj < 8; jj++) {
                        int a0 = acc[ii * 8 + jj];
                        a0 = __dp4a(av[ii].x, bv[jj].x, a0);
                        a0 = __dp4a(av[ii].y, bv[jj].y, a0);
                        acc[ii * 8 + jj] = a0;
                    }
            }
        }
    }

    // epilogue: add integer bias, convert to f32, store
    if (is_tensor) {
        #pragma unroll
        for (int nt = 0; nt < 8; nt++) {
            int col = bn0 + nt * 8 + ((lane & 3) << 1);
            int2 bv = *reinterpret_cast<const int2*>(&g_bias[p * OO + col]);
            #pragma unroll
            for (int mt = 0; mt < 2; mt++) {
                int row0 = bm0 + wm * 32 + mt * 16 + (lane >> 2);
                float2 v0, v1;
                v0.x = (float)(acc[mt * 32 + nt * 4 + 0] + bv.x);
                v0.y = (float)(acc[mt * 32 + nt * 4 + 1] + bv.y);
                v1.x = (float)(acc[mt * 32 + nt * 4 + 2] + bv.x);
                v1.y = (float)(acc[mt * 32 + nt * 4 + 3] + bv.y);
                *reinterpret_cast<float2*>(out + ((size_t)p * BB + row0) * OO + col) = v0;
                *reinterpret_cast<float2*>(out + ((size_t)p * BB + row0 + 8) * OO + col) = v1;
            }
        }
    } else {
        int biasr[8];
        #pragma unroll
        for (int jj = 0; jj < 8; jj++)
            biasr[jj] = g_bias[p * OO + bn0 + 64 + tx + 8 * jj];
        #pragma unroll
        for (int ii = 0; ii < 8; ii++) {
            int row = bm0 + wm * 32 + ty + 4 * ii;
            float* orow = out + ((size_t)p * BB + row) * OO + bn0 + 64 + tx;
            #pragma unroll
            for (int jj = 0; jj < 8; jj++)
                orow[8 * jj] = (float)(acc[ii * 8 + jj] + biasr[jj]);
        }
    }
}

// ---------------- launch: graph fork — prep on stream 0, gemm chunks on s2/s3 ----------------
extern "C" void kernel_launch(void* const* d_in, const int* in_sizes, int n_in,
                              void* d_out, int out_size) {
    const float* x = (const float*)d_in[0];
    const float* w = (const float*)d_in[1];
    if (n_in >= 2 && in_sizes[0] > in_sizes[1]) {   // safety: x is the smaller tensor
        const float* t = x; x = w; w = t;
    }
    float* out = (float*)d_out;

    static cudaStream_t s2 = nullptr, s3 = nullptr;
    static cudaEvent_t evP[NGROUPS], evJ2, evJ3;
    if (!s2) {   // first call is the uncaptured correctness run: create resources once
        cudaStreamCreateWithFlags(&s2, cudaStreamNonBlocking);
        cudaStreamCreateWithFlags(&s3, cudaStreamNonBlocking);
        for (int g = 0; g < NGROUPS; g++)
            cudaEventCreateWithFlags(&evP[g], cudaEventDisableTiming);
        cudaEventCreateWithFlags(&evJ2, cudaEventDisableTiming);
        cudaEventCreateWithFlags(&evJ3, cudaEventDisableTiming);
        cudaFuncSetAttribute(k_gemm, cudaFuncAttributeMaxDynamicSharedMemorySize, SMEM_TOTAL);
    }

    // stream 0: convert, then prep chunks (each publishes an event)
    k_convert_x<<<(PP * BB * II) / (16 * 256), 256>>>(x);
    for (int g = 0; g < NGROUPS; g++) {
        k_prep_w<<<dim3(II / 32, OO / 32, PGROUP), 256>>>(w, g * PGROUP);
        cudaEventRecord(evP[g], 0);
    }

    // side streams: gemm chunk g waits only on prep chunk g
    for (int g = 0; g < NGROUPS; g++) {
        cudaStream_t sg = (g & 1) ? s3 : s2;
        cudaStreamWaitEvent(sg, evP[g], 0);
        k_gemm<<<dim3(OO / BN, BB / BM, PGROUP), 256, SMEM_TOTAL, sg>>>(out, g * PGROUP);
    }

    // join forks back into stream 0 so the captured graph has a single terminal
    cudaEventRecord(evJ2, s2);
    cudaEventRecord(evJ3, s3);
    cudaStreamWaitEvent(0, evJ2, 0);
    cudaStreamWaitEvent(0, evJ3, 0);
}